// round 9
// baseline (speedup 1.0000x reference)
#include <cuda_runtime.h>
#include <math.h>

// Shapes (fixed by the problem)
#define B_   2
#define H_   8
#define N_   64
#define TD_  1024          // T*D = 32*32
#define BH_  (B_ * H_)     // 16
#define INV_SCALE_ (1.0f / 32.0f)   // 1/sqrt(T*D)

#define KCH_  64                 // k-elements per chunk
#define NCH_  (TD_ / KCH_)       // 16 chunks
#define SSTR_ 65                 // smem row stride (odd -> conflict-free)

#define PREF_J_ 16               // V rows prefetched to L2 pre-sync in kernel B

// Partial scores, row-major: [chunk][bh][i][j].  16*16*64*64 floats = 4 MB
__device__ float g_part[NCH_ * BH_ * N_ * N_];

// ---------------------------------------------------------------------------
// Kernel A: partial QK^T. grid = NCH_*BH_ = 256 blocks, 512 threads.
// 4x2 register blocking over a 64x64 score tile (k chunk = 64).
// Restaged through smem so the global store is coalesced row-major.
// ---------------------------------------------------------------------------
__global__ __launch_bounds__(512, 2)
void qk_part_kernel(const float* __restrict__ Q,
                    const float* __restrict__ K)
{
#if __CUDA_ARCH__ >= 900
    cudaTriggerProgrammaticLaunchCompletion();
#endif

    __shared__ float sQ[N_ * SSTR_];
    __shared__ float sK[N_ * SSTR_];

    const int bx = blockIdx.x;
    const int bh = bx & (BH_ - 1);
    const int c  = bx >> 4;          // chunk index 0..15
    const int tid = threadIdx.x;     // 0..511

    // Fill: 4096 floats per tile, 8 per thread, coalesced.
#pragma unroll
    for (int it = 0; it < 8; ++it) {
        int idx = tid + 512 * it;
        int row = idx >> 6;          // 0..63
        int col = idx & 63;          // 0..63
        size_t g = (size_t)(bh * N_ + row) * TD_ + c * KCH_ + col;
        sQ[row * SSTR_ + col] = Q[g];
        sK[row * SSTR_ + col] = K[g];
    }
    __syncthreads();

    const int ty = tid & 15;         // row group  0..15
    const int tx = tid >> 4;         // col group  0..31

    float acc[4][2];
#pragma unroll
    for (int m = 0; m < 4; ++m)
#pragma unroll
        for (int n = 0; n < 2; ++n) acc[m][n] = 0.0f;

#pragma unroll 4
    for (int k = 0; k < KCH_; ++k) {
        float q[4], kk[2];
#pragma unroll
        for (int m = 0; m < 4; ++m) q[m]  = sQ[(ty + 16 * m) * SSTR_ + k];
#pragma unroll
        for (int n = 0; n < 2; ++n) kk[n] = sK[(tx + 32 * n) * SSTR_ + k];
#pragma unroll
        for (int m = 0; m < 4; ++m)
#pragma unroll
            for (int n = 0; n < 2; ++n)
                acc[m][n] += q[m] * kk[n];
    }

    // Restage through smem (reuse sQ; 64x65 fits in 64*SSTR_).
    __syncthreads();                 // everyone done reading sQ/sK
#pragma unroll
    for (int m = 0; m < 4; ++m)
#pragma unroll
        for (int n = 0; n < 2; ++n)
            sQ[(ty + 16 * m) * SSTR_ + (tx + 32 * n)] = acc[m][n];
    __syncthreads();

    // Coalesced row-major store: g_part[c][bh][row][col]
    float* dst = g_part + ((size_t)c * BH_ + bh) * (N_ * N_);
#pragma unroll
    for (int it = 0; it < 8; ++it) {
        int idx = tid + 512 * it;
        int row = idx >> 6;
        int col = idx & 63;
        dst[idx] = sQ[row * SSTR_ + col];
    }
}

// ---------------------------------------------------------------------------
// Kernel B (R7, unchanged): per-(bh,i) softmax + streaming V pass.
// grid = BH*N = 1024 blocks, 256 threads. PDL overlaps prologue with A.
// ---------------------------------------------------------------------------
__global__ __launch_bounds__(256, 4)
void attn_v_kernel(const float* __restrict__ V,
                   const int*   __restrict__ mask,
                   float*       __restrict__ out)
{
    const int bx   = blockIdx.x;          // 0 .. BH*N-1
    const int i    = bx % N_;
    const int bh   = bx / N_;
    const int tid  = threadIdx.x;
    const int lane = tid & 31;
    const int warp = tid >> 5;

    __shared__ float s_attn[N_];

    // ---- Pre-sync (independent of kernel A's output) ----
    const float4* Vbase = reinterpret_cast<const float4*>(V) +
                          ((size_t)bh * N_ * N_ + i) * (TD_ / 4) + tid;
    const size_t jstride = (size_t)N_ * (TD_ / 4);   // float4 stride between j's

    // Prefetch the first PREF_J_ V rows into L2 while A still runs.
#pragma unroll
    for (int j = 0; j < PREF_J_; ++j)
        asm volatile("prefetch.global.L2 [%0];" :: "l"(Vbase + (size_t)j * jstride));

    // Mask loads (input, not produced by A)
    int m0 = 1, m1 = 1;
    if (warp == 0) {
        const size_t roff = ((size_t)bh * N_ + i) * N_;
        m0 = mask[roff + lane];
        m1 = mask[roff + lane + 32];
    }

    // ---- Wait for kernel A's g_part to be visible ----
#if __CUDA_ARCH__ >= 900
    cudaGridDependencySynchronize();
#endif

    // warp 0: gather partial scores (coalesced), sum, mask, softmax
    if (warp == 0) {
        const float* base = g_part + ((size_t)bh * N_ + i) * N_;
        float v0 = 0.0f, v1 = 0.0f;
#pragma unroll
        for (int cch = 0; cch < NCH_; ++cch) {
            const float* p = base + (size_t)cch * (BH_ * N_ * N_);
            v0 += p[lane];
            v1 += p[lane + 32];
        }
        v0 *= INV_SCALE_;
        v1 *= INV_SCALE_;

        if (m0 == 0) v0 = -INFINITY;
        if (m1 == 0) v1 = -INFINITY;

        float mx = fmaxf(v0, v1);
#pragma unroll
        for (int o = 16; o > 0; o >>= 1) mx = fmaxf(mx, __shfl_xor_sync(0xffffffffu, mx, o));
        float e0 = __expf(v0 - mx);
        float e1 = __expf(v1 - mx);
        float s = e0 + e1;
#pragma unroll
        for (int o = 16; o > 0; o >>= 1) s += __shfl_xor_sync(0xffffffffu, s, o);
        float inv = 1.0f / s;
        s_attn[lane]      = e0 * inv;
        s_attn[lane + 32] = e1 * inv;
    }
    __syncthreads();

    // streaming contraction: out[tf] = sum_j attn[j] * V[bh, j, i, tf]
    float4 acc = make_float4(0.f, 0.f, 0.f, 0.f);

#pragma unroll
    for (int j0 = 0; j0 < N_; j0 += 8) {
        float4 v[8];
#pragma unroll
        for (int jj = 0; jj < 8; ++jj)
            v[jj] = __ldcs(&Vbase[(size_t)(j0 + jj) * jstride]);
#pragma unroll
        for (int jj = 0; jj < 8; ++jj) {
            float a = s_attn[j0 + jj];
            acc.x += a * v[jj].x;
            acc.y += a * v[jj].y;
            acc.z += a * v[jj].z;
            acc.w += a * v[jj].w;
        }
    }

    float4* Orow = reinterpret_cast<float4*>(out + (size_t)(bh * N_ + i) * TD_);
    __stcs(&Orow[tid], acc);
}

extern "C" void kernel_launch(void* const* d_in, const int* in_sizes, int n_in,
                              void* d_out, int out_size)
{
    const float* Q    = (const float*)d_in[0];
    const float* K    = (const float*)d_in[1];
    const float* V    = (const float*)d_in[2];
    const int*   mask = (const int*)d_in[3];
    float*       out  = (float*)d_out;

    // Kernel A: normal launch
    qk_part_kernel<<<NCH_ * BH_, 512>>>(Q, K);

    // Kernel B: programmatic dependent launch (overlaps prologue with A)
    cudaLaunchConfig_t cfg = {};
    cfg.gridDim  = dim3(BH_ * N_);
    cfg.blockDim = dim3(256);
    cfg.dynamicSmemBytes = 0;
    cudaLaunchAttribute attrs[1];
    attrs[0].id = cudaLaunchAttributeProgrammaticStreamSerialization;
    attrs[0].val.programmaticStreamSerializationAllowed = 1;
    cfg.attrs = attrs;
    cfg.numAttrs = 1;
    cudaLaunchKernelEx(&cfg, attn_v_kernel, V, mask, out);
}

// round 10
// speedup vs baseline: 1.0007x; 1.0007x over previous
#include <cuda_runtime.h>
#include <math.h>

// Shapes (fixed by the problem)
#define B_   2
#define H_   8
#define N_   64
#define TD_  1024          // T*D = 32*32
#define BH_  (B_ * H_)     // 16
#define INV_SCALE_ (1.0f / 32.0f)   // 1/sqrt(T*D)

#define KCH_  64                 // k-elements per chunk
#define NCH_  (TD_ / KCH_)       // 16 chunks
#define SSTR_ 65                 // smem row stride (odd -> conflict-free)
#define IH_   32                 // i-rows per A block (i-split)

#define PREF_J_ 16               // V rows prefetched to L2 pre-sync in kernel B

// Partial scores, row-major: [chunk][bh][i][j].  16*16*64*64 floats = 4 MB
__device__ float g_part[NCH_ * BH_ * N_ * N_];

// ---------------------------------------------------------------------------
// Kernel A: partial QK^T. grid = NCH_*BH_*2 = 512 blocks, 256 threads.
// Each block: 32x64 score tile (i-half) over one 64-wide k chunk,
// 2x4 register blocking. Restaged through smem for coalesced stores.
// ---------------------------------------------------------------------------
__global__ __launch_bounds__(256, 4)
void qk_part_kernel(const float* __restrict__ Q,
                    const float* __restrict__ K)
{
#if __CUDA_ARCH__ >= 900
    cudaTriggerProgrammaticLaunchCompletion();
#endif

    __shared__ float sQ[IH_ * SSTR_];   // 32 x 65
    __shared__ float sK[N_  * SSTR_];   // 64 x 65

    const int bx  = blockIdx.x;          // 0..511
    const int ih  = bx & 1;              // i-half
    const int bh  = (bx >> 1) & (BH_ - 1);
    const int c   = bx >> 5;             // chunk index 0..15
    const int tid = threadIdx.x;
    const int i0  = ih * IH_;

    // Fill K tile: 4096 floats, 16/thread, coalesced.
#pragma unroll
    for (int it = 0; it < 16; ++it) {
        int idx = tid + 256 * it;
        int row = idx >> 6;
        int col = idx & 63;
        sK[row * SSTR_ + col] = K[(size_t)(bh * N_ + row) * TD_ + c * KCH_ + col];
    }
    // Fill Q tile (32 rows): 2048 floats, 8/thread, coalesced.
#pragma unroll
    for (int it = 0; it < 8; ++it) {
        int idx = tid + 256 * it;
        int row = idx >> 6;
        int col = idx & 63;
        sQ[row * SSTR_ + col] = Q[(size_t)(bh * N_ + i0 + row) * TD_ + c * KCH_ + col];
    }
    __syncthreads();

    const int ty = tid & 15;         // row group 0..15 -> rows ty, ty+16
    const int tx = tid >> 4;         // col group 0..15 -> cols tx+16n

    float acc[2][4];
#pragma unroll
    for (int m = 0; m < 2; ++m)
#pragma unroll
        for (int n = 0; n < 4; ++n) acc[m][n] = 0.0f;

#pragma unroll 4
    for (int k = 0; k < KCH_; ++k) {
        float q[2], kk[4];
#pragma unroll
        for (int m = 0; m < 2; ++m) q[m]  = sQ[(ty + 16 * m) * SSTR_ + k];
#pragma unroll
        for (int n = 0; n < 4; ++n) kk[n] = sK[(tx + 16 * n) * SSTR_ + k];
#pragma unroll
        for (int m = 0; m < 2; ++m)
#pragma unroll
            for (int n = 0; n < 4; ++n)
                acc[m][n] += q[m] * kk[n];
    }

    // Restage through smem (reuse sQ: 32x65) for coalesced global store.
    __syncthreads();
#pragma unroll
    for (int m = 0; m < 2; ++m)
#pragma unroll
        for (int n = 0; n < 4; ++n)
            sQ[(ty + 16 * m) * SSTR_ + (tx + 16 * n)] = acc[m][n];
    __syncthreads();

    // Coalesced row-major store: g_part[c][bh][i0+row][col]
    float* dst = g_part + ((size_t)c * BH_ + bh) * (N_ * N_) + i0 * N_;
#pragma unroll
    for (int it = 0; it < 8; ++it) {
        int idx = tid + 256 * it;    // 0..2047
        int row = idx >> 6;
        int col = idx & 63;
        dst[idx] = sQ[row * SSTR_ + col];
    }
}

// ---------------------------------------------------------------------------
// Kernel B (R7, unchanged): per-(bh,i) softmax + streaming V pass.
// grid = BH*N = 1024 blocks, 256 threads. PDL overlaps prologue with A.
// ---------------------------------------------------------------------------
__global__ __launch_bounds__(256, 4)
void attn_v_kernel(const float* __restrict__ V,
                   const int*   __restrict__ mask,
                   float*       __restrict__ out)
{
    const int bx   = blockIdx.x;          // 0 .. BH*N-1
    const int i    = bx % N_;
    const int bh   = bx / N_;
    const int tid  = threadIdx.x;
    const int lane = tid & 31;
    const int warp = tid >> 5;

    __shared__ float s_attn[N_];

    // ---- Pre-sync (independent of kernel A's output) ----
    const float4* Vbase = reinterpret_cast<const float4*>(V) +
                          ((size_t)bh * N_ * N_ + i) * (TD_ / 4) + tid;
    const size_t jstride = (size_t)N_ * (TD_ / 4);   // float4 stride between j's

    // Prefetch the first PREF_J_ V rows into L2 while A still runs.
#pragma unroll
    for (int j = 0; j < PREF_J_; ++j)
        asm volatile("prefetch.global.L2 [%0];" :: "l"(Vbase + (size_t)j * jstride));

    // Mask loads (input, not produced by A)
    int m0 = 1, m1 = 1;
    if (warp == 0) {
        const size_t roff = ((size_t)bh * N_ + i) * N_;
        m0 = mask[roff + lane];
        m1 = mask[roff + lane + 32];
    }

    // ---- Wait for kernel A's g_part to be visible ----
#if __CUDA_ARCH__ >= 900
    cudaGridDependencySynchronize();
#endif

    // warp 0: gather partial scores (coalesced), sum, mask, softmax
    if (warp == 0) {
        const float* base = g_part + ((size_t)bh * N_ + i) * N_;
        float v0 = 0.0f, v1 = 0.0f;
#pragma unroll
        for (int cch = 0; cch < NCH_; ++cch) {
            const float* p = base + (size_t)cch * (BH_ * N_ * N_);
            v0 += p[lane];
            v1 += p[lane + 32];
        }
        v0 *= INV_SCALE_;
        v1 *= INV_SCALE_;

        if (m0 == 0) v0 = -INFINITY;
        if (m1 == 0) v1 = -INFINITY;

        float mx = fmaxf(v0, v1);
#pragma unroll
        for (int o = 16; o > 0; o >>= 1) mx = fmaxf(mx, __shfl_xor_sync(0xffffffffu, mx, o));
        float e0 = __expf(v0 - mx);
        float e1 = __expf(v1 - mx);
        float s = e0 + e1;
#pragma unroll
        for (int o = 16; o > 0; o >>= 1) s += __shfl_xor_sync(0xffffffffu, s, o);
        float inv = 1.0f / s;
        s_attn[lane]      = e0 * inv;
        s_attn[lane + 32] = e1 * inv;
    }
    __syncthreads();

    // streaming contraction: out[tf] = sum_j attn[j] * V[bh, j, i, tf]
    float4 acc = make_float4(0.f, 0.f, 0.f, 0.f);

#pragma unroll
    for (int j0 = 0; j0 < N_; j0 += 8) {
        float4 v[8];
#pragma unroll
        for (int jj = 0; jj < 8; ++jj)
            v[jj] = __ldcs(&Vbase[(size_t)(j0 + jj) * jstride]);
#pragma unroll
        for (int jj = 0; jj < 8; ++jj) {
            float a = s_attn[j0 + jj];
            acc.x += a * v[jj].x;
            acc.y += a * v[jj].y;
            acc.z += a * v[jj].z;
            acc.w += a * v[jj].w;
        }
    }

    float4* Orow = reinterpret_cast<float4*>(out + (size_t)(bh * N_ + i) * TD_);
    __stcs(&Orow[tid], acc);
}

extern "C" void kernel_launch(void* const* d_in, const int* in_sizes, int n_in,
                              void* d_out, int out_size)
{
    const float* Q    = (const float*)d_in[0];
    const float* K    = (const float*)d_in[1];
    const float* V    = (const float*)d_in[2];
    const int*   mask = (const int*)d_in[3];
    float*       out  = (float*)d_out;

    // Kernel A: normal launch
    qk_part_kernel<<<NCH_ * BH_ * 2, 256>>>(Q, K);

    // Kernel B: programmatic dependent launch (overlaps prologue with A)
    cudaLaunchConfig_t cfg = {};
    cfg.gridDim  = dim3(BH_ * N_);
    cfg.blockDim = dim3(256);
    cfg.dynamicSmemBytes = 0;
    cudaLaunchAttribute attrs[1];
    attrs[0].id = cudaLaunchAttributeProgrammaticStreamSerialization;
    attrs[0].val.programmaticStreamSerializationAllowed = 1;
    cfg.attrs = attrs;
    cfg.numAttrs = 1;
    cudaLaunchKernelEx(&cfg, attn_v_kernel, V, mask, out);
}

// round 11
// speedup vs baseline: 1.0163x; 1.0156x over previous
#include <cuda_runtime.h>
#include <math.h>

// Shapes (fixed by the problem)
#define B_   2
#define H_   8
#define N_   64
#define TD_  1024          // T*D = 32*32
#define BH_  (B_ * H_)     // 16
#define INV_SCALE_ (1.0f / 32.0f)   // 1/sqrt(T*D)

#define KCH_  64                 // k-elements per chunk
#define NCH_  (TD_ / KCH_)       // 16 chunks
#define SSTR_ 65                 // smem row stride (odd -> conflict-free)

#define PREF_J_ 16               // V rows prefetched to L2 pre-sync in kernel B

// Partial scores, row-major: [chunk][bh][i][j].  16*16*64*64 floats = 4 MB
__device__ float g_part[NCH_ * BH_ * N_ * N_];

// ---------------------------------------------------------------------------
// Kernel A (R7, measured best overlap): partial QK^T.
// grid = NCH_*BH_ = 256 blocks, 256 threads, occ 2.
// 4x4 register blocking; restaged through smem for coalesced stores.
// ---------------------------------------------------------------------------
__global__ __launch_bounds__(256, 2)
void qk_part_kernel(const float* __restrict__ Q,
                    const float* __restrict__ K)
{
#if __CUDA_ARCH__ >= 900
    cudaTriggerProgrammaticLaunchCompletion();
#endif

    __shared__ float sQ[N_ * SSTR_];
    __shared__ float sK[N_ * SSTR_];

    const int bx = blockIdx.x;
    const int bh = bx & (BH_ - 1);
    const int c  = bx >> 4;          // chunk index 0..15
    const int tid = threadIdx.x;

    // Fill: 4096 floats per tile, 16 per thread, coalesced.
#pragma unroll
    for (int it = 0; it < 16; ++it) {
        int idx = tid + 256 * it;
        int row = idx >> 6;          // 0..63
        int col = idx & 63;          // 0..63
        size_t g = (size_t)(bh * N_ + row) * TD_ + c * KCH_ + col;
        sQ[row * SSTR_ + col] = Q[g];
        sK[row * SSTR_ + col] = K[g];
    }
    __syncthreads();

    const int ty = tid & 15;         // row group
    const int tx = tid >> 4;         // col group

    float acc[4][4];
#pragma unroll
    for (int m = 0; m < 4; ++m)
#pragma unroll
        for (int n = 0; n < 4; ++n) acc[m][n] = 0.0f;

#pragma unroll 4
    for (int k = 0; k < KCH_; ++k) {
        float q[4], kk[4];
#pragma unroll
        for (int m = 0; m < 4; ++m) q[m]  = sQ[(ty + 16 * m) * SSTR_ + k];
#pragma unroll
        for (int n = 0; n < 4; ++n) kk[n] = sK[(tx + 16 * n) * SSTR_ + k];
#pragma unroll
        for (int m = 0; m < 4; ++m)
#pragma unroll
            for (int n = 0; n < 4; ++n)
                acc[m][n] += q[m] * kk[n];
    }

    // Restage through smem (reuse sQ) so the global store is coalesced.
    __syncthreads();                 // everyone done reading sQ/sK
#pragma unroll
    for (int m = 0; m < 4; ++m)
#pragma unroll
        for (int n = 0; n < 4; ++n)
            sQ[(ty + 16 * m) * SSTR_ + (tx + 16 * n)] = acc[m][n];
    __syncthreads();

    // Coalesced row-major store: g_part[c][bh][row][col]
    float* dst = g_part + ((size_t)c * BH_ + bh) * (N_ * N_);
#pragma unroll
    for (int it = 0; it < 16; ++it) {
        int idx = tid + 256 * it;
        int row = idx >> 6;
        int col = idx & 63;
        dst[idx] = sQ[row * SSTR_ + col];
    }
}

// ---------------------------------------------------------------------------
// Kernel B: per-(bh,i) softmax + streaming V pass.
// grid = BH*N = 1024 blocks, 256 threads, occ 5 (software-pipelined depth-4
// double buffer keeps regs ~48). PDL overlaps prologue with A.
// ---------------------------------------------------------------------------
__global__ __launch_bounds__(256, 5)
void attn_v_kernel(const float* __restrict__ V,
                   const int*   __restrict__ mask,
                   float*       __restrict__ out)
{
    const int bx   = blockIdx.x;          // 0 .. BH*N-1
    const int i    = bx % N_;
    const int bh   = bx / N_;
    const int tid  = threadIdx.x;
    const int lane = tid & 31;
    const int warp = tid >> 5;

    __shared__ float s_attn[N_];

    // ---- Pre-sync (independent of kernel A's output) ----
    const float4* Vbase = reinterpret_cast<const float4*>(V) +
                          ((size_t)bh * N_ * N_ + i) * (TD_ / 4) + tid;
    const size_t jstride = (size_t)N_ * (TD_ / 4);   // float4 stride between j's

    // Prefetch the first PREF_J_ V rows into L2 while A still runs.
#pragma unroll
    for (int j = 0; j < PREF_J_; ++j)
        asm volatile("prefetch.global.L2 [%0];" :: "l"(Vbase + (size_t)j * jstride));

    // Mask loads (input, not produced by A)
    int m0 = 1, m1 = 1;
    if (warp == 0) {
        const size_t roff = ((size_t)bh * N_ + i) * N_;
        m0 = mask[roff + lane];
        m1 = mask[roff + lane + 32];
    }

    // ---- Wait for kernel A's g_part to be visible ----
#if __CUDA_ARCH__ >= 900
    cudaGridDependencySynchronize();
#endif

    // warp 0: gather partial scores (coalesced), sum, mask, softmax
    if (warp == 0) {
        const float* base = g_part + ((size_t)bh * N_ + i) * N_;
        float v0 = 0.0f, v1 = 0.0f;
#pragma unroll
        for (int cch = 0; cch < NCH_; ++cch) {
            const float* p = base + (size_t)cch * (BH_ * N_ * N_);
            v0 += p[lane];
            v1 += p[lane + 32];
        }
        v0 *= INV_SCALE_;
        v1 *= INV_SCALE_;

        if (m0 == 0) v0 = -INFINITY;
        if (m1 == 0) v1 = -INFINITY;

        float mx = fmaxf(v0, v1);
#pragma unroll
        for (int o = 16; o > 0; o >>= 1) mx = fmaxf(mx, __shfl_xor_sync(0xffffffffu, mx, o));
        float e0 = __expf(v0 - mx);
        float e1 = __expf(v1 - mx);
        float s = e0 + e1;
#pragma unroll
        for (int o = 16; o > 0; o >>= 1) s += __shfl_xor_sync(0xffffffffu, s, o);
        float inv = 1.0f / s;
        s_attn[lane]      = e0 * inv;
        s_attn[lane + 32] = e1 * inv;
    }
    __syncthreads();

    // streaming contraction, software-pipelined (depth-4 double buffer):
    // out[tf] = sum_j attn[j] * V[bh, j, i, tf]
    float4 acc = make_float4(0.f, 0.f, 0.f, 0.f);
    float4 v[4];

#pragma unroll
    for (int jj = 0; jj < 4; ++jj)
        v[jj] = __ldcs(&Vbase[(size_t)jj * jstride]);

#pragma unroll
    for (int j0 = 0; j0 < N_; j0 += 4) {
        float4 w[4];
        if (j0 + 4 < N_) {
#pragma unroll
            for (int jj = 0; jj < 4; ++jj)
                w[jj] = __ldcs(&Vbase[(size_t)(j0 + 4 + jj) * jstride]);
        }
#pragma unroll
        for (int jj = 0; jj < 4; ++jj) {
            float a = s_attn[j0 + jj];
            acc.x += a * v[jj].x;
            acc.y += a * v[jj].y;
            acc.z += a * v[jj].z;
            acc.w += a * v[jj].w;
        }
#pragma unroll
        for (int jj = 0; jj < 4; ++jj) v[jj] = w[jj];
    }

    float4* Orow = reinterpret_cast<float4*>(out + (size_t)(bh * N_ + i) * TD_);
    __stcs(&Orow[tid], acc);
}

extern "C" void kernel_launch(void* const* d_in, const int* in_sizes, int n_in,
                              void* d_out, int out_size)
{
    const float* Q    = (const float*)d_in[0];
    const float* K    = (const float*)d_in[1];
    const float* V    = (const float*)d_in[2];
    const int*   mask = (const int*)d_in[3];
    float*       out  = (float*)d_out;

    // Kernel A: normal launch
    qk_part_kernel<<<NCH_ * BH_, 256>>>(Q, K);

    // Kernel B: programmatic dependent launch (overlaps prologue with A)
    cudaLaunchConfig_t cfg = {};
    cfg.gridDim  = dim3(BH_ * N_);
    cfg.blockDim = dim3(256);
    cfg.dynamicSmemBytes = 0;
    cudaLaunchAttribute attrs[1];
    attrs[0].id = cudaLaunchAttributeProgrammaticStreamSerialization;
    attrs[0].val.programmaticStreamSerializationAllowed = 1;
    cfg.attrs = attrs;
    cfg.numAttrs = 1;
    cudaLaunchKernelEx(&cfg, attn_v_kernel, V, mask, out);
}

// round 12
// speedup vs baseline: 1.0513x; 1.0344x over previous
#include <cuda_runtime.h>
#include <math.h>

// Shapes (fixed by the problem)
#define B_   2
#define H_   8
#define N_   64
#define TD_  1024          // T*D = 32*32
#define BH_  (B_ * H_)     // 16
#define INV_SCALE_ (1.0f / 32.0f)   // 1/sqrt(T*D)

#define KCH_  64                 // k-elements per chunk
#define NCH_  (TD_ / KCH_)       // 16 chunks
#define SSTR_ 65                 // smem row stride (odd -> conflict-free)

#define PREF_J_ 16               // V rows prefetched to L2 pre-sync in kernel B

// Partial scores, row-major: [chunk][bh][i][j].  16*16*64*64 floats = 4 MB
__device__ float g_part[NCH_ * BH_ * N_ * N_];

// ---------------------------------------------------------------------------
// Kernel A (R7, measured best overlap): partial QK^T.
// grid = NCH_*BH_ = 256 blocks, 256 threads, occ 2.
// 4x4 register blocking; restaged through smem for coalesced stores.
// ---------------------------------------------------------------------------
__global__ __launch_bounds__(256, 2)
void qk_part_kernel(const float* __restrict__ Q,
                    const float* __restrict__ K)
{
#if __CUDA_ARCH__ >= 900
    cudaTriggerProgrammaticLaunchCompletion();
#endif

    __shared__ float sQ[N_ * SSTR_];
    __shared__ float sK[N_ * SSTR_];

    const int bx = blockIdx.x;
    const int bh = bx & (BH_ - 1);
    const int c  = bx >> 4;          // chunk index 0..15
    const int tid = threadIdx.x;

    // Fill: 4096 floats per tile, 16 per thread, coalesced.
#pragma unroll
    for (int it = 0; it < 16; ++it) {
        int idx = tid + 256 * it;
        int row = idx >> 6;          // 0..63
        int col = idx & 63;          // 0..63
        size_t g = (size_t)(bh * N_ + row) * TD_ + c * KCH_ + col;
        sQ[row * SSTR_ + col] = Q[g];
        sK[row * SSTR_ + col] = K[g];
    }
    __syncthreads();

    const int ty = tid & 15;         // row group
    const int tx = tid >> 4;         // col group

    float acc[4][4];
#pragma unroll
    for (int m = 0; m < 4; ++m)
#pragma unroll
        for (int n = 0; n < 4; ++n) acc[m][n] = 0.0f;

#pragma unroll 4
    for (int k = 0; k < KCH_; ++k) {
        float q[4], kk[4];
#pragma unroll
        for (int m = 0; m < 4; ++m) q[m]  = sQ[(ty + 16 * m) * SSTR_ + k];
#pragma unroll
        for (int n = 0; n < 4; ++n) kk[n] = sK[(tx + 16 * n) * SSTR_ + k];
#pragma unroll
        for (int m = 0; m < 4; ++m)
#pragma unroll
            for (int n = 0; n < 4; ++n)
                acc[m][n] += q[m] * kk[n];
    }

    // Restage through smem (reuse sQ) so the global store is coalesced.
    __syncthreads();                 // everyone done reading sQ/sK
#pragma unroll
    for (int m = 0; m < 4; ++m)
#pragma unroll
        for (int n = 0; n < 4; ++n)
            sQ[(ty + 16 * m) * SSTR_ + (tx + 16 * n)] = acc[m][n];
    __syncthreads();

    // Coalesced row-major store: g_part[c][bh][row][col]
    float* dst = g_part + ((size_t)c * BH_ + bh) * (N_ * N_);
#pragma unroll
    for (int it = 0; it < 16; ++it) {
        int idx = tid + 256 * it;
        int row = idx >> 6;
        int col = idx & 63;
        dst[idx] = sQ[row * SSTR_ + col];
    }
}

// ---------------------------------------------------------------------------
// Kernel B: per-(bh,i) softmax + streaming V pass.
// grid = BH*N = 1024 blocks, 256 threads, occ 4, 8-deep load batches.
// First V batch is hoisted ABOVE the softmax so DRAM stays busy during the
// per-CTA serial prologue. PDL overlaps prologue with kernel A.
// ---------------------------------------------------------------------------
__global__ __launch_bounds__(256, 4)
void attn_v_kernel(const float* __restrict__ V,
                   const int*   __restrict__ mask,
                   float*       __restrict__ out)
{
    const int bx   = blockIdx.x;          // 0 .. BH*N-1
    const int i    = bx % N_;
    const int bh   = bx / N_;
    const int tid  = threadIdx.x;
    const int lane = tid & 31;
    const int warp = tid >> 5;

    __shared__ float s_attn[N_];

    // ---- Pre-sync (independent of kernel A's output) ----
    const float4* Vbase = reinterpret_cast<const float4*>(V) +
                          ((size_t)bh * N_ * N_ + i) * (TD_ / 4) + tid;
    const size_t jstride = (size_t)N_ * (TD_ / 4);   // float4 stride between j's

    // Prefetch the first PREF_J_ V rows into L2 while A still runs.
#pragma unroll
    for (int j = 0; j < PREF_J_; ++j)
        asm volatile("prefetch.global.L2 [%0];" :: "l"(Vbase + (size_t)j * jstride));

    // Mask loads (input, not produced by A)
    int m0 = 1, m1 = 1;
    if (warp == 0) {
        const size_t roff = ((size_t)bh * N_ + i) * N_;
        m0 = mask[roff + lane];
        m1 = mask[roff + lane + 32];
    }

    // ---- Wait for kernel A's g_part to be visible ----
#if __CUDA_ARCH__ >= 900
    cudaGridDependencySynchronize();
#endif

    // Issue the first V batch NOW (independent of s_attn) so the memory pipe
    // is full while warp 0 runs the softmax prologue.
    float4 v[8];
#pragma unroll
    for (int jj = 0; jj < 8; ++jj)
        v[jj] = __ldcs(&Vbase[(size_t)jj * jstride]);

    // warp 0: gather partial scores (coalesced), sum, mask, softmax
    if (warp == 0) {
        const float* base = g_part + ((size_t)bh * N_ + i) * N_;
        float v0 = 0.0f, v1 = 0.0f;
#pragma unroll
        for (int cch = 0; cch < NCH_; ++cch) {
            const float* p = base + (size_t)cch * (BH_ * N_ * N_);
            v0 += p[lane];
            v1 += p[lane + 32];
        }
        v0 *= INV_SCALE_;
        v1 *= INV_SCALE_;

        if (m0 == 0) v0 = -INFINITY;
        if (m1 == 0) v1 = -INFINITY;

        float mx = fmaxf(v0, v1);
#pragma unroll
        for (int o = 16; o > 0; o >>= 1) mx = fmaxf(mx, __shfl_xor_sync(0xffffffffu, mx, o));
        float e0 = __expf(v0 - mx);
        float e1 = __expf(v1 - mx);
        float s = e0 + e1;
#pragma unroll
        for (int o = 16; o > 0; o >>= 1) s += __shfl_xor_sync(0xffffffffu, s, o);
        float inv = 1.0f / s;
        s_attn[lane]      = e0 * inv;
        s_attn[lane + 32] = e1 * inv;
    }
    __syncthreads();

    // streaming contraction: out[tf] = sum_j attn[j] * V[bh, j, i, tf]
    // Batch n is consumed, then batch n+1 is loaded into the same registers.
    float4 acc = make_float4(0.f, 0.f, 0.f, 0.f);

#pragma unroll
    for (int j0 = 0; j0 < N_; j0 += 8) {
#pragma unroll
        for (int jj = 0; jj < 8; ++jj) {
            float a = s_attn[j0 + jj];
            acc.x += a * v[jj].x;
            acc.y += a * v[jj].y;
            acc.z += a * v[jj].z;
            acc.w += a * v[jj].w;
        }
        if (j0 + 8 < N_) {
#pragma unroll
            for (int jj = 0; jj < 8; ++jj)
                v[jj] = __ldcs(&Vbase[(size_t)(j0 + 8 + jj) * jstride]);
        }
    }

    float4* Orow = reinterpret_cast<float4*>(out + (size_t)(bh * N_ + i) * TD_);
    __stcs(&Orow[tid], acc);
}

extern "C" void kernel_launch(void* const* d_in, const int* in_sizes, int n_in,
                              void* d_out, int out_size)
{
    const float* Q    = (const float*)d_in[0];
    const float* K    = (const float*)d_in[1];
    const float* V    = (const float*)d_in[2];
    const int*   mask = (const int*)d_in[3];
    float*       out  = (float*)d_out;

    // Kernel A: normal launch
    qk_part_kernel<<<NCH_ * BH_, 256>>>(Q, K);

    // Kernel B: programmatic dependent launch (overlaps prologue with A)
    cudaLaunchConfig_t cfg = {};
    cfg.gridDim  = dim3(BH_ * N_);
    cfg.blockDim = dim3(256);
    cfg.dynamicSmemBytes = 0;
    cudaLaunchAttribute attrs[1];
    attrs[0].id = cudaLaunchAttributeProgrammaticStreamSerialization;
    attrs[0].val.programmaticStreamSerializationAllowed = 1;
    cfg.attrs = attrs;
    cfg.numAttrs = 1;
    cudaLaunchKernelEx(&cfg, attn_v_kernel, V, mask, out);
}